// round 8
// baseline (speedup 1.0000x reference)
#include <cuda_runtime.h>
#include <cuda_fp16.h>
#include <cstdint>

// ----------------------------------------------------------------------------
// InstantNGP hash encoding (16 levels, 2^19 table, 2 feats) fused with a
// 32->64->64->64->16 fp32 MLP.
//   - MLP weights in __constant__ memory (LDC port, off the L1 pipe).
//   - TWO POINTS PER THREAD: each LDC.128 weight load feeds 4 fma.rn.f32x2
//     (2 per point), halving constant-port pressure per point. The 8-cyc
//     LDC->LDC structural floor was the hidden binder (occupancy increase in
//     R5 gave zero speedup).
//   - fp32 activation slab [64][256] in SMEM, full-width in-place layers.
//   - table dtype (fp16/fp32/bf16) probed at runtime inside the prep kernel.
// ----------------------------------------------------------------------------

#define NUM_LEVEL 16
#define LOG_T 19
#define TABLE_SIZE (1u << LOG_T)
#define TABLE_MASK (TABLE_SIZE - 1u)

#define TPB  128           // threads per block
#define PPB  256           // points per block (2 per thread)
#define COLS 256           // slab row width (2 columns per thread)

// Transposed-weight layout (floats); all offsets 16B-aligned.
#define OFF_WINT  0        // wT_in  [32][64]
#define OFF_BIN   2048     // b_in   [64]
#define OFF_WH0T  2112     // wT_h0  [64][64]
#define OFF_BH0   6208     // b_h0   [64]
#define OFF_WH1T  6272     // wT_h1  [64][64]
#define OFF_BH1   10368    // b_h1   [64]
#define OFF_WOUTT 10432    // wT_out [64][16]
#define OFF_BOUT  11456    // b_out  [16]
#define W_TOTAL   11472

__device__ float g_wT[W_TOTAL];
__device__ int   g_tab_mode;       // 0 = half2, 1 = float2, 2 = bf16x2
__constant__ __align__(16) float c_wT[W_TOTAL];

// ---------------------------------------------------------------- packed f32x2
__device__ __forceinline__ unsigned long long pack2(float a, float b) {
    unsigned long long r;
    asm("mov.b64 %0, {%1,%2};" : "=l"(r) : "f"(a), "f"(b));
    return r;
}
__device__ __forceinline__ void unpack2(unsigned long long v, float& a, float& b) {
    asm("mov.b64 {%0,%1}, %2;" : "=f"(a), "=f"(b) : "l"(v));
}
__device__ __forceinline__ unsigned long long fma2(unsigned long long a,
                                                   unsigned long long b,
                                                   unsigned long long c) {
    unsigned long long d;
    asm("fma.rn.f32x2 %0, %1, %2, %3;" : "=l"(d) : "l"(a), "l"(b), "l"(c));
    return d;
}

// ------------------------------------------------- prep (+ parallel probe)
__global__ void prep_weights_kernel(
    const float* __restrict__ w_in, const float* __restrict__ b_in,
    const float* __restrict__ w_h0, const float* __restrict__ b_h0,
    const float* __restrict__ w_h1, const float* __restrict__ b_h1,
    const float* __restrict__ w_out, const float* __restrict__ b_out,
    const unsigned int* __restrict__ tab) {
    int t = blockIdx.x * blockDim.x + threadIdx.x;
    int stride = gridDim.x * blockDim.x;

    if (blockIdx.x == 0 && threadIdx.x < 32) {
        int tiny = 0, lowband = 0;
        for (int i = 0; i < 8; i++) {
            unsigned int w = tab[(threadIdx.x * 8 + i) * 97 + 1];
            float fh = __uint_as_float(w);
            float fl = __uint_as_float(w << 16);
            if (fabsf(fh) < 1e-20f) tiny++;
            float al = fabsf(fl);
            if (al > 1e-6f && al < 1e-2f) lowband++;
        }
        tiny    = __reduce_add_sync(0xFFFFFFFFu, tiny);
        lowband = __reduce_add_sync(0xFFFFFFFFu, lowband);
        if (threadIdx.x == 0)
            g_tab_mode = (tiny > 128) ? 0 : ((lowband > 128) ? 2 : 1);
    }

    for (int k = t; k < 2048; k += stride)          // 32x64
        g_wT[OFF_WINT + k] = w_in[(k & 63) * 32 + (k >> 6)];
    for (int k = t; k < 64; k += stride)
        g_wT[OFF_BIN + k] = b_in[k];
    for (int k = t; k < 4096; k += stride)          // 64x64
        g_wT[OFF_WH0T + k] = w_h0[(k & 63) * 64 + (k >> 6)];
    for (int k = t; k < 64; k += stride)
        g_wT[OFF_BH0 + k] = b_h0[k];
    for (int k = t; k < 4096; k += stride)          // 64x64
        g_wT[OFF_WH1T + k] = w_h1[(k & 63) * 64 + (k >> 6)];
    for (int k = t; k < 64; k += stride)
        g_wT[OFF_BH1 + k] = b_h1[k];
    for (int k = t; k < 1024; k += stride)          // 64x16
        g_wT[OFF_WOUTT + k] = w_out[(k & 15) * 64 + (k >> 4)];
    for (int k = t; k < 16; k += stride)
        g_wT[OFF_BOUT + k] = b_out[k];
}

// --------------------------------------------- constant-memory weight reads
__device__ __forceinline__ ulonglong2 cw2(int foff) {        // 16B from cmem
    return *(const ulonglong2*)&c_wT[foff];
}
__device__ __forceinline__ unsigned long long cb1(int foff) { // 8B from cmem
    return *(const unsigned long long*)&c_wT[foff];
}

// ---------------------------------------------------------------- table fetch
template <int MODE>
__device__ __forceinline__ float2 tab_fetch(const void* __restrict__ base,
                                            unsigned idx) {
    if (MODE == 0) {
        __half2 v = __ldg(((const __half2*)base) + idx);
        return __half22float2(v);
    } else if (MODE == 1) {
        return __ldg(((const float2*)base) + idx);
    } else {
        unsigned int w = __ldg(((const unsigned int*)base) + idx);
        return make_float2(__uint_as_float(w << 16),
                           __uint_as_float(w & 0xFFFF0000u));
    }
}

// --------------------------------------- encode 2 points (features only)
template <int MODE>
__device__ __forceinline__ void encode_levels2(
    const char* __restrict__ tables,
    float c0x, float c0y, float c0z,
    float c1x, float c1y, float c1z,
    float* __restrict__ xs, int t) {
    // floor(16 * 2^(l/3)) for l = 0..15
    const float RES[NUM_LEVEL] = {16.f, 20.f, 25.f, 32.f, 40.f, 50.f, 64.f, 80.f,
                                  101.f, 128.f, 161.f, 203.f, 256.f, 322.f, 406.f, 512.f};
    const int ELEM_BYTES = (MODE == 1) ? 8 : 4;

#pragma unroll
    for (int l = 0; l < NUM_LEVEL; l++) {
        float r = RES[l];
        const void* tab = tables + (size_t)l * TABLE_SIZE * ELEM_BYTES;

        // --- point 0 hash setup ---
        float s0x = c0x * r, s0y = c0y * r, s0z = c0z * r;
        float f0x = floorf(s0x), f0y = floorf(s0y), f0z = floorf(s0z);
        float g0x = ceilf(s0x), g0y = ceilf(s0y), g0z = ceilf(s0z);
        float a0x = s0x - f0x, a0y = s0y - f0y, a0z = s0z - f0z;
        float b0x = g0x - s0x, b0y = g0y - s0y, b0z = g0z - s0z;
        unsigned hx00 = (unsigned)(int)f0x;
        unsigned hx01 = (unsigned)(int)g0x;
        unsigned hy00 = (unsigned)(int)f0y * 2654435761u;
        unsigned hy01 = (unsigned)(int)g0y * 2654435761u;
        unsigned hz00 = (unsigned)(int)f0z * 805459861u;
        unsigned hz01 = (unsigned)(int)g0z * 805459861u;

        // --- point 1 hash setup ---
        float s1x = c1x * r, s1y = c1y * r, s1z = c1z * r;
        float f1x = floorf(s1x), f1y = floorf(s1y), f1z = floorf(s1z);
        float g1x = ceilf(s1x), g1y = ceilf(s1y), g1z = ceilf(s1z);
        float a1x = s1x - f1x, a1y = s1y - f1y, a1z = s1z - f1z;
        float b1x = g1x - s1x, b1y = g1y - s1y, b1z = g1z - s1z;
        unsigned hx10 = (unsigned)(int)f1x;
        unsigned hx11 = (unsigned)(int)g1x;
        unsigned hy10 = (unsigned)(int)f1y * 2654435761u;
        unsigned hy11 = (unsigned)(int)g1y * 2654435761u;
        unsigned hz10 = (unsigned)(int)f1z * 805459861u;
        unsigned hz11 = (unsigned)(int)g1z * 805459861u;

        // Issue all 16 gathers, then consume.
        float2 t0[8], t1[8];
#pragma unroll
        for (int o = 0; o < 8; o++) {
            unsigned h0 = ((o & 4) ? hx01 : hx00) ^ ((o & 2) ? hy01 : hy00) ^
                          ((o & 1) ? hz01 : hz00);
            unsigned h1 = ((o & 4) ? hx11 : hx10) ^ ((o & 2) ? hy11 : hy10) ^
                          ((o & 1) ? hz11 : hz10);
            t0[o] = tab_fetch<MODE>(tab, h0 & TABLE_MASK);
            t1[o] = tab_fetch<MODE>(tab, h1 & TABLE_MASK);
        }

        float p0f0 = 0.0f, p0f1 = 0.0f, p1f0 = 0.0f, p1f1 = 0.0f;
#pragma unroll
        for (int o = 0; o < 8; o++) {
            // corner uses ceil where bit set -> weight uses the floor distance
            float w0 = ((o & 4) ? a0x : b0x) * ((o & 2) ? a0y : b0y) *
                       ((o & 1) ? a0z : b0z);
            float w1 = ((o & 4) ? a1x : b1x) * ((o & 2) ? a1y : b1y) *
                       ((o & 1) ? a1z : b1z);
            p0f0 = fmaf(t0[o].x, w0, p0f0);
            p0f1 = fmaf(t0[o].y, w0, p0f1);
            p1f0 = fmaf(t1[o].x, w1, p1f0);
            p1f1 = fmaf(t1[o].y, w1, p1f1);
        }
        xs[(2 * l) * COLS + t]           = p0f0;
        xs[(2 * l) * COLS + t + TPB]     = p1f0;
        xs[(2 * l + 1) * COLS + t]       = p0f1;
        xs[(2 * l + 1) * COLS + t + TPB] = p1f1;
    }
}

// --------------------------------------------- MLP layer, 2 points, in-place
template <int WOFF, int BOFF, int IN, int OUT>
__device__ __forceinline__ void mlp_layer_relu2(float* __restrict__ xs, int t) {
    unsigned long long a0[OUT / 2], a1[OUT / 2];
#pragma unroll
    for (int j = 0; j < OUT / 2; j++) { a0[j] = cb1(BOFF + 2 * j); a1[j] = a0[j]; }
#pragma unroll 2
    for (int i = 0; i < IN; i++) {
        float x0v = xs[i * COLS + t];
        float x1v = xs[i * COLS + t + TPB];
        unsigned long long x0 = pack2(x0v, x0v);
        unsigned long long x1 = pack2(x1v, x1v);
#pragma unroll
        for (int q = 0; q < OUT / 4; q++) {
            ulonglong2 w = cw2(WOFF + i * OUT + 4 * q);                // LDC.128
            a0[2 * q]     = fma2(w.x, x0, a0[2 * q]);
            a0[2 * q + 1] = fma2(w.y, x0, a0[2 * q + 1]);
            a1[2 * q]     = fma2(w.x, x1, a1[2 * q]);
            a1[2 * q + 1] = fma2(w.y, x1, a1[2 * q + 1]);
        }
    }
    // All reads done; in-place write-back is safe (own columns only).
#pragma unroll
    for (int j = 0; j < OUT / 2; j++) {
        float u, v, p, q;
        unpack2(a0[j], u, v);
        unpack2(a1[j], p, q);
        u = fmaxf(u, 0.0f); v = fmaxf(v, 0.0f);
        p = fmaxf(p, 0.0f); q = fmaxf(q, 0.0f);
        xs[(2 * j) * COLS + t]           = u;
        xs[(2 * j) * COLS + t + TPB]     = p;
        xs[(2 * j + 1) * COLS + t]       = v;
        xs[(2 * j + 1) * COLS + t + TPB] = q;
    }
}

template <int WOFF, int BOFF, int IN, int OUT>
__device__ __forceinline__ void mlp_final2(const float* __restrict__ xs, int t,
                                           float* __restrict__ out0,
                                           float* __restrict__ out1) {
    unsigned long long a0[OUT / 2], a1[OUT / 2];
#pragma unroll
    for (int j = 0; j < OUT / 2; j++) { a0[j] = cb1(BOFF + 2 * j); a1[j] = a0[j]; }
#pragma unroll 2
    for (int i = 0; i < IN; i++) {
        float x0v = xs[i * COLS + t];
        float x1v = xs[i * COLS + t + TPB];
        unsigned long long x0 = pack2(x0v, x0v);
        unsigned long long x1 = pack2(x1v, x1v);
#pragma unroll
        for (int q = 0; q < OUT / 4; q++) {
            ulonglong2 w = cw2(WOFF + i * OUT + 4 * q);
            a0[2 * q]     = fma2(w.x, x0, a0[2 * q]);
            a0[2 * q + 1] = fma2(w.y, x0, a0[2 * q + 1]);
            a1[2 * q]     = fma2(w.x, x1, a1[2 * q]);
            a1[2 * q + 1] = fma2(w.y, x1, a1[2 * q + 1]);
        }
    }
    float v0[OUT], v1[OUT];
#pragma unroll
    for (int j = 0; j < OUT / 2; j++) {
        unpack2(a0[j], v0[2 * j], v0[2 * j + 1]);
        unpack2(a1[j], v1[2 * j], v1[2 * j + 1]);
    }
    float4* o0 = (float4*)out0;
    float4* o1 = (float4*)out1;
#pragma unroll
    for (int q = 0; q < OUT / 4; q++) {
        o0[q] = make_float4(v0[4 * q], v0[4 * q + 1], v0[4 * q + 2], v0[4 * q + 3]);
        o1[q] = make_float4(v1[4 * q], v1[4 * q + 1], v1[4 * q + 2], v1[4 * q + 3]);
    }
}

// ---------------------------------------------------------------- main kernel
__global__ __launch_bounds__(TPB, 3) void nerf_fused_kernel(
    const float* __restrict__ coords,
    const char* __restrict__ tables,
    float* __restrict__ out) {
    extern __shared__ float xs[];   // [64][COLS] fp32 activation slab

    int t = threadIdx.x;
    int p0 = blockIdx.x * PPB + 2 * t;      // thread owns points p0, p0+1
    float c0x = coords[3 * p0 + 0];
    float c0y = coords[3 * p0 + 1];
    float c0z = coords[3 * p0 + 2];
    float c1x = coords[3 * p0 + 3];
    float c1y = coords[3 * p0 + 4];
    float c1z = coords[3 * p0 + 5];

    int mode = g_tab_mode;   // uniform across grid
    if (mode == 1)
        encode_levels2<1>(tables, c0x, c0y, c0z, c1x, c1y, c1z, xs, t);
    else if (mode == 0)
        encode_levels2<0>(tables, c0x, c0y, c0z, c1x, c1y, c1z, xs, t);
    else
        encode_levels2<2>(tables, c0x, c0y, c0z, c1x, c1y, c1z, xs, t);

    // MLP (fp32, packed f32x2 FMAs, weights via LDC, each load feeds 2 pts).
    mlp_layer_relu2<OFF_WINT, OFF_BIN, 32, 64>(xs, t);
    mlp_layer_relu2<OFF_WH0T, OFF_BH0, 64, 64>(xs, t);
    mlp_layer_relu2<OFF_WH1T, OFF_BH1, 64, 64>(xs, t);
    mlp_final2<OFF_WOUTT, OFF_BOUT, 64, 16>(xs, t,
                                            out + (size_t)p0 * 16,
                                            out + (size_t)(p0 + 1) * 16);
}

// ---------------------------------------------------------------- launch
extern "C" void kernel_launch(void* const* d_in, const int* in_sizes, int n_in,
                              void* d_out, int out_size) {
    const float* coords = (const float*)d_in[0];
    const char* tables  = (const char*)d_in[1];
    const float* w_in  = (const float*)d_in[2];
    const float* b_in  = (const float*)d_in[3];
    const float* w_h0  = (const float*)d_in[4];
    const float* b_h0  = (const float*)d_in[5];
    const float* w_h1  = (const float*)d_in[6];
    const float* b_h1  = (const float*)d_in[7];
    const float* w_out = (const float*)d_in[8];
    const float* b_out = (const float*)d_in[9];
    float* out = (float*)d_out;

    int n = in_sizes[0] / 3;

    prep_weights_kernel<<<32, 256>>>(w_in, b_in, w_h0, b_h0, w_h1, b_h1,
                                     w_out, b_out, (const unsigned int*)tables);

    // Copy prepared weights into the constant bank (D2D, graph-capturable).
    void* g_addr = nullptr;
    cudaGetSymbolAddress(&g_addr, g_wT);
    cudaMemcpyToSymbolAsync(c_wT, g_addr, W_TOTAL * sizeof(float), 0,
                            cudaMemcpyDeviceToDevice);

    const int smem_bytes = 64 * COLS * sizeof(float);  // 65536
    cudaFuncSetAttribute(nerf_fused_kernel,
                         cudaFuncAttributeMaxDynamicSharedMemorySize, smem_bytes);
    nerf_fused_kernel<<<n / PPB, TPB, smem_bytes>>>(coords, tables, out);
}